// round 9
// baseline (speedup 1.0000x reference)
#include <cuda_runtime.h>
#include <cuda_bf16.h>
#include <cstdint>

#define N_NODES 100000
#define N_EDGES 800000
#define D_IN    256
#define D_OUT   128

#define KPADW   268              // padded k-stride in words (268%32=12 -> conflict-free)
#define TILES   1563             // ceil(100000 / 64)
#define GRID_P  148              // persistent CTAs
#define SCAT_BLOCKS 50000        // N_EDGES*16/256

// Aggregation buffer: [N_NODES][128] = [agg_a(0:64) | agg_b(64:128)].
// BSS-zeroed at load; gemm re-zeroes each tile after consuming it.
__device__ __align__(16) float g_x[(size_t)N_NODES * 128];

// W^T tf32 image: [n=128][k=268 padded], k pair-permuted within 8-groups
// (order 0,4,1,5,2,6,3,7) so (qp, qp+4) fragment pairs are word-adjacent.
__device__ __align__(16) uint32_t g_wt[128 * KPADW];

__device__ __forceinline__ uint32_t f2tf32(float f) {
    uint32_t u;
    asm("cvt.rna.tf32.f32 %0, %1;" : "=r"(u) : "f"(f));
    return u;
}

// position of original k within its 8-group under pair permutation
__device__ __forceinline__ int kperm(int k) {
    return (k & ~7) | (((k & 3) << 1) | ((k >> 2) & 1));
}

// ---------------------------------------------------------------------------
// Kernel 1: fused scatter-add (both edge types per thread) + W prep blocks.
// Edge reads use evict_first policy via cache_hint operand form (streaming);
// atomics use evict_last policy so g_x stays L2-resident.
// ---------------------------------------------------------------------------
__global__ void scatter_prep_kernel(const float* __restrict__ edata_a,
                                    const int* __restrict__ recv_a,
                                    const float* __restrict__ edata_b,
                                    const int* __restrict__ recv_b,
                                    const float* __restrict__ W) {
    if (blockIdx.x >= SCAT_BLOCKS) {
        int idx = (blockIdx.x - SCAT_BLOCKS) * 256 + threadIdx.x;
        if (idx < D_IN * D_OUT) {
            int n = idx & 127;
            int k = idx >> 7;
            g_wt[n * KPADW + kperm(k)] = f2tf32(W[k * D_OUT + n]);
        }
        return;
    }
    int idx = blockIdx.x * 256 + threadIdx.x;      // 0 .. 12.8M-1
    int edge = idx >> 4;
    int q    = idx & 15;

    uint64_t pol_ef, pol_el;
    asm("createpolicy.fractional.L2::evict_first.b64 %0, 1.0;" : "=l"(pol_ef));
    asm("createpolicy.fractional.L2::evict_last.b64 %0, 1.0;"  : "=l"(pol_el));

    const float4* pa = reinterpret_cast<const float4*>(edata_a) + (size_t)edge * 16 + q;
    const float4* pb = reinterpret_cast<const float4*>(edata_b) + (size_t)edge * 16 + q;
    float4 va, vb;
    asm volatile("ld.global.nc.L2::cache_hint.v4.f32 {%0,%1,%2,%3}, [%4], %5;"
                 : "=f"(va.x), "=f"(va.y), "=f"(va.z), "=f"(va.w)
                 : "l"(pa), "l"(pol_ef));
    asm volatile("ld.global.nc.L2::cache_hint.v4.f32 {%0,%1,%2,%3}, [%4], %5;"
                 : "=f"(vb.x), "=f"(vb.y), "=f"(vb.z), "=f"(vb.w)
                 : "l"(pb), "l"(pol_ef));

    int ra = recv_a[edge];
    int rb = recv_b[edge];
    float* da = g_x + (size_t)ra * 128 + q * 4;
    float* db = g_x + (size_t)rb * 128 + 64 + q * 4;

    asm volatile("red.global.L2::cache_hint.add.v4.f32 [%0], {%1, %2, %3, %4}, %5;"
                 :: "l"(da), "f"(va.x), "f"(va.y), "f"(va.z), "f"(va.w), "l"(pol_el)
                 : "memory");
    asm volatile("red.global.L2::cache_hint.add.v4.f32 [%0], {%1, %2, %3, %4}, %5;"
                 :: "l"(db), "f"(vb.x), "f"(vb.y), "f"(vb.z), "f"(vb.w), "l"(pol_el)
                 : "memory");
}

// ---------------------------------------------------------------------------
__device__ __forceinline__ void mma_tf32(float* d, uint32_t a0, uint32_t a1,
                                         uint32_t a2, uint32_t a3,
                                         uint32_t b0, uint32_t b1) {
    asm volatile(
        "mma.sync.aligned.m16n8k8.row.col.f32.tf32.tf32.f32 "
        "{%0,%1,%2,%3}, {%4,%5,%6,%7}, {%8,%9}, {%0,%1,%2,%3};"
        : "+f"(d[0]), "+f"(d[1]), "+f"(d[2]), "+f"(d[3])
        : "r"(a0), "r"(a1), "r"(a2), "r"(a3), "r"(b0), "r"(b1));
}

// SMEM layout (uint32 words): sW [0, 34304), sX [34304, 51456)
#define SW_BASE 0
#define SX_BASE 34304
#define SMEM_WORDS 51456       // 205824 bytes

// ---------------------------------------------------------------------------
// Kernel 2: persistent TF32 HMMA GEMM, LDS.64 fragment loads.
// 512 threads / 16 warps, W staged once, tiles strided, reg-prefetch.
// ---------------------------------------------------------------------------
__global__ __launch_bounds__(512, 1)
void gemm_mma_kernel(const float* __restrict__ vdata,
                     const float* __restrict__ bias,
                     float* __restrict__ out) {
    extern __shared__ uint32_t smem[];
    const int tid  = threadIdx.x;
    const int wid  = tid >> 5;
    const int lane = tid & 31;
    const int grp  = lane >> 2;
    const int qp   = lane & 3;

    const int m0 = (wid & 3) * 16;    // warp M band (of 64)
    const int n0 = (wid >> 2) * 32;   // warp N quarter (of 128)

    // ---- Stage W^T image once (8576 uint4) ----
    {
        const uint4* src = reinterpret_cast<const uint4*>(g_wt);
        uint4* dst = reinterpret_cast<uint4*>(smem + SW_BASE);
        #pragma unroll
        for (int i = 0; i < 17; i++) {
            int j = i * 512 + tid;
            if (j < 128 * KPADW / 4) dst[j] = src[j];
        }
    }

    float2 bv[4];
    #pragma unroll
    for (int j = 0; j < 4; j++)
        bv[j] = *reinterpret_cast<const float2*>(bias + n0 + j * 8 + qp * 2);

    const float4* A4 = reinterpret_cast<const float4*>(g_x);
    const float4* V4 = reinterpret_cast<const float4*>(vdata);

    int t = blockIdx.x;
    float4 xr[8];

    if (t < TILES) {
        int node0 = t * 64;
        #pragma unroll
        for (int i = 0; i < 8; i++) {
            int j = i * 512 + tid;
            int r = j >> 6, c4 = j & 63;
            int node = node0 + r;
            float4 v = make_float4(0.f, 0.f, 0.f, 0.f);
            if (node < N_NODES)
                v = (c4 < 32) ? A4[(size_t)node * 32 + c4]
                              : V4[(size_t)node * 32 + (c4 - 32)];
            xr[i] = v;
        }
    }

    while (t < TILES) {
        const int node0 = t * 64;

        // ---- convert regs -> smem tf32 (pair-permuted); re-zero g_x region ----
        #pragma unroll
        for (int i = 0; i < 8; i++) {
            int j = i * 512 + tid;
            int r = j >> 6, c4 = j & 63;
            float4 v = xr[i];
            // k = 4*c4 + {0..3}; group base = (c4>>1)*8; c4 even -> pos 2i, odd -> 2i+1
            int base = SX_BASE + r * KPADW + (c4 >> 1) * 8 + (c4 & 1);
            smem[base + 0] = f2tf32(v.x);
            smem[base + 2] = f2tf32(v.y);
            smem[base + 4] = f2tf32(v.z);
            smem[base + 6] = f2tf32(v.w);
            if (c4 < 32) {
                int node = node0 + r;
                if (node < N_NODES)
                    reinterpret_cast<float4*>(g_x)[(size_t)node * 32 + c4] =
                        make_float4(0.f, 0.f, 0.f, 0.f);
            }
        }
        __syncthreads();

        // ---- prefetch next tile during compute ----
        int tn = t + GRID_P;
        if (tn < TILES) {
            int nn0 = tn * 64;
            #pragma unroll
            for (int i = 0; i < 8; i++) {
                int j = i * 512 + tid;
                int r = j >> 6, c4 = j & 63;
                int node = nn0 + r;
                float4 v = make_float4(0.f, 0.f, 0.f, 0.f);
                if (node < N_NODES)
                    v = (c4 < 32) ? A4[(size_t)node * 32 + c4]
                                  : V4[(size_t)node * 32 + (c4 - 32)];
                xr[i] = v;
            }
        }

        // ---- compute: 32 k-steps x 4 n-tiles, LDS.64 fragments ----
        float acc[4][4];
        #pragma unroll
        for (int j = 0; j < 4; j++)
            #pragma unroll
            for (int c = 0; c < 4; c++) acc[j][c] = 0.f;

        const uint2* s2 = reinterpret_cast<const uint2*>(smem);
        #pragma unroll 8
        for (int ks = 0; ks < 32; ks++) {
            int wA = (SX_BASE + (m0 + grp) * KPADW + ks * 8 + 2 * qp) >> 1;
            uint2 aA = s2[wA];                    // a0 (k=qp), a2 (k=qp+4)
            uint2 aB = s2[wA + 4 * KPADW];        // row+8: a1, a3

            #pragma unroll
            for (int j = 0; j < 4; j++) {
                int wB = (SW_BASE + (n0 + j * 8 + grp) * KPADW + ks * 8 + 2 * qp) >> 1;
                uint2 b = s2[wB];                 // b0 (k=qp), b1 (k=qp+4)
                mma_tf32(acc[j], aA.x, aB.x, aA.y, aB.y, b.x, b.y);
            }
        }

        // ---- epilogue ----
        int row_a = node0 + m0 + grp;
        int row_b = row_a + 8;
        #pragma unroll
        for (int j = 0; j < 4; j++) {
            int col = n0 + j * 8 + qp * 2;
            if (row_a < N_NODES) {
                float2 o = make_float2(acc[j][0] + bv[j].x, acc[j][1] + bv[j].y);
                *reinterpret_cast<float2*>(out + (size_t)row_a * D_OUT + col) = o;
            }
            if (row_b < N_NODES) {
                float2 o = make_float2(acc[j][2] + bv[j].x, acc[j][3] + bv[j].y);
                *reinterpret_cast<float2*>(out + (size_t)row_b * D_OUT + col) = o;
            }
        }
        __syncthreads();
        t = tn;
    }
}

// ---------------------------------------------------------------------------
extern "C" void kernel_launch(void* const* d_in, const int* in_sizes, int n_in,
                              void* d_out, int out_size) {
    const float* vdata   = (const float*)d_in[0];
    const float* edata_a = (const float*)d_in[1];
    const float* edata_b = (const float*)d_in[2];
    const int*   conn_a  = (const int*)d_in[3];
    const int*   conn_b  = (const int*)d_in[4];
    const float* W       = (const float*)d_in[5];
    const float* bias    = (const float*)d_in[6];
    float*       out     = (float*)d_out;

    scatter_prep_kernel<<<SCAT_BLOCKS + 128, 256>>>(
        edata_a, conn_a + N_EDGES, edata_b, conn_b + N_EDGES, W);

    {
        size_t smem_bytes = SMEM_WORDS * sizeof(uint32_t);   // 205824
        cudaFuncSetAttribute(gemm_mma_kernel,
                             cudaFuncAttributeMaxDynamicSharedMemorySize,
                             (int)smem_bytes);
        gemm_mma_kernel<<<GRID_P, 512, smem_bytes>>>(vdata, bias, out);
    }
}

// round 10
// speedup vs baseline: 1.1737x; 1.1737x over previous
#include <cuda_runtime.h>
#include <cuda_bf16.h>
#include <cstdint>

#define N_NODES 100000
#define N_EDGES 800000
#define D_IN    256
#define D_OUT   128

#define KPADW   264              // row stride in words; 264%32=8 -> LDS.64 conflict-free
#define TILES   1563             // ceil(100000 / 64)
#define GRID_P  148              // persistent CTAs
#define SCAT_BLOCKS 50000        // N_EDGES*16/256

// Aggregation buffer: [N_NODES][128] = [agg_a(0:64) | agg_b(64:128)].
// BSS-zeroed at load; gemm re-zeroes each tile after consuming it.
__device__ __align__(16) float g_x[(size_t)N_NODES * 128];

// W^T tf32 image: [n=128][k=264 padded], k pair-permuted within 8-groups
// (order 0,4,1,5,2,6,3,7) so (qp, qp+4) fragment pairs are word-adjacent.
__device__ __align__(16) uint32_t g_wt[128 * KPADW];

__device__ __forceinline__ uint32_t f2tf32(float f) {
    uint32_t u;
    asm("cvt.rna.tf32.f32 %0, %1;" : "=r"(u) : "f"(f));
    return u;
}

// position of original k within its 8-group under pair permutation
__device__ __forceinline__ int kperm(int k) {
    return (k & ~7) | (((k & 3) << 1) | ((k >> 2) & 1));
}

// ---------------------------------------------------------------------------
// Kernel 1: fused scatter-add (both edge types per thread) + W prep blocks.
// Edge reads: evict_first policy (streaming); atomics: evict_last policy so
// g_x stays L2-resident.   (unchanged from round 9 — measured ~86us)
// ---------------------------------------------------------------------------
__global__ void scatter_prep_kernel(const float* __restrict__ edata_a,
                                    const int* __restrict__ recv_a,
                                    const float* __restrict__ edata_b,
                                    const int* __restrict__ recv_b,
                                    const float* __restrict__ W) {
    if (blockIdx.x >= SCAT_BLOCKS) {
        int idx = (blockIdx.x - SCAT_BLOCKS) * 256 + threadIdx.x;
        if (idx < D_IN * D_OUT) {
            int n = idx & 127;
            int k = idx >> 7;
            g_wt[n * KPADW + kperm(k)] = f2tf32(W[k * D_OUT + n]);
        }
        return;
    }
    int idx = blockIdx.x * 256 + threadIdx.x;      // 0 .. 12.8M-1
    int edge = idx >> 4;
    int q    = idx & 15;

    uint64_t pol_ef, pol_el;
    asm("createpolicy.fractional.L2::evict_first.b64 %0, 1.0;" : "=l"(pol_ef));
    asm("createpolicy.fractional.L2::evict_last.b64 %0, 1.0;"  : "=l"(pol_el));

    const float4* pa = reinterpret_cast<const float4*>(edata_a) + (size_t)edge * 16 + q;
    const float4* pb = reinterpret_cast<const float4*>(edata_b) + (size_t)edge * 16 + q;
    float4 va, vb;
    asm volatile("ld.global.nc.L2::cache_hint.v4.f32 {%0,%1,%2,%3}, [%4], %5;"
                 : "=f"(va.x), "=f"(va.y), "=f"(va.z), "=f"(va.w)
                 : "l"(pa), "l"(pol_ef));
    asm volatile("ld.global.nc.L2::cache_hint.v4.f32 {%0,%1,%2,%3}, [%4], %5;"
                 : "=f"(vb.x), "=f"(vb.y), "=f"(vb.z), "=f"(vb.w)
                 : "l"(pb), "l"(pol_ef));

    int ra = recv_a[edge];
    int rb = recv_b[edge];
    float* da = g_x + (size_t)ra * 128 + q * 4;
    float* db = g_x + (size_t)rb * 128 + 64 + q * 4;

    asm volatile("red.global.L2::cache_hint.add.v4.f32 [%0], {%1, %2, %3, %4}, %5;"
                 :: "l"(da), "f"(va.x), "f"(va.y), "f"(va.z), "f"(va.w), "l"(pol_el)
                 : "memory");
    asm volatile("red.global.L2::cache_hint.add.v4.f32 [%0], {%1, %2, %3, %4}, %5;"
                 :: "l"(db), "f"(vb.x), "f"(vb.y), "f"(vb.z), "f"(vb.w), "l"(pol_el)
                 : "memory");
}

// ---------------------------------------------------------------------------
__device__ __forceinline__ void mma_tf32(float* d, uint32_t a0, uint32_t a1,
                                         uint32_t a2, uint32_t a3,
                                         uint32_t b0, uint32_t b1) {
    asm volatile(
        "mma.sync.aligned.m16n8k8.row.col.f32.tf32.tf32.f32 "
        "{%0,%1,%2,%3}, {%4,%5,%6,%7}, {%8,%9}, {%0,%1,%2,%3};"
        : "+f"(d[0]), "+f"(d[1]), "+f"(d[2]), "+f"(d[3])
        : "r"(a0), "r"(a1), "r"(a2), "r"(a3), "r"(b0), "r"(b1));
}

// SMEM layout (uint32 words): sW [0, 33792), sX [33792, 50688)
#define SW_BASE 0
#define SX_BASE 33792
#define SMEM_WORDS 50688       // 202752 bytes

// ---------------------------------------------------------------------------
// Kernel 2: persistent TF32 HMMA GEMM, LDS.64 fragment loads, conflict-free.
// 512 threads / 16 warps, W staged once, tiles strided, reg-prefetch.
// ---------------------------------------------------------------------------
__global__ __launch_bounds__(512, 1)
void gemm_mma_kernel(const float* __restrict__ vdata,
                     const float* __restrict__ bias,
                     float* __restrict__ out) {
    extern __shared__ uint32_t smem[];
    const int tid  = threadIdx.x;
    const int wid  = tid >> 5;
    const int lane = tid & 31;
    const int grp  = lane >> 2;
    const int qp   = lane & 3;

    const int m0 = (wid & 3) * 16;    // warp M band (of 64)
    const int n0 = (wid >> 2) * 32;   // warp N quarter (of 128)

    // ---- Stage W^T image once (128*264 words = 8448 uint4) ----
    {
        const uint4* src = reinterpret_cast<const uint4*>(g_wt);
        uint4* dst = reinterpret_cast<uint4*>(smem + SW_BASE);
        #pragma unroll
        for (int i = 0; i < 17; i++) {
            int j = i * 512 + tid;
            if (j < 128 * KPADW / 4) dst[j] = src[j];
        }
    }

    float2 bv[4];
    #pragma unroll
    for (int j = 0; j < 4; j++)
        bv[j] = *reinterpret_cast<const float2*>(bias + n0 + j * 8 + qp * 2);

    const float4* A4 = reinterpret_cast<const float4*>(g_x);
    const float4* V4 = reinterpret_cast<const float4*>(vdata);

    int t = blockIdx.x;
    float4 xr[8];

    if (t < TILES) {
        int node0 = t * 64;
        #pragma unroll
        for (int i = 0; i < 8; i++) {
            int j = i * 512 + tid;
            int r = j >> 6, c4 = j & 63;
            int node = node0 + r;
            float4 v = make_float4(0.f, 0.f, 0.f, 0.f);
            if (node < N_NODES)
                v = (c4 < 32) ? A4[(size_t)node * 32 + c4]
                              : V4[(size_t)node * 32 + (c4 - 32)];
            xr[i] = v;
        }
    }

    while (t < TILES) {
        const int node0 = t * 64;

        // ---- convert regs -> smem tf32 (pair-permuted); re-zero g_x region ----
        #pragma unroll
        for (int i = 0; i < 8; i++) {
            int j = i * 512 + tid;
            int r = j >> 6, c4 = j & 63;
            float4 v = xr[i];
            // k = 4*c4 + {0..3}; group base = (c4>>1)*8; even c4 -> slot 2i, odd -> 2i+1
            int base = SX_BASE + r * KPADW + (c4 >> 1) * 8 + (c4 & 1);
            smem[base + 0] = f2tf32(v.x);
            smem[base + 2] = f2tf32(v.y);
            smem[base + 4] = f2tf32(v.z);
            smem[base + 6] = f2tf32(v.w);
            if (c4 < 32) {
                int node = node0 + r;
                if (node < N_NODES)
                    reinterpret_cast<float4*>(g_x)[(size_t)node * 32 + c4] =
                        make_float4(0.f, 0.f, 0.f, 0.f);
            }
        }
        __syncthreads();

        // ---- prefetch next tile during compute ----
        int tn = t + GRID_P;
        if (tn < TILES) {
            int nn0 = tn * 64;
            #pragma unroll
            for (int i = 0; i < 8; i++) {
                int j = i * 512 + tid;
                int r = j >> 6, c4 = j & 63;
                int node = nn0 + r;
                float4 v = make_float4(0.f, 0.f, 0.f, 0.f);
                if (node < N_NODES)
                    v = (c4 < 32) ? A4[(size_t)node * 32 + c4]
                                  : V4[(size_t)node * 32 + (c4 - 32)];
                xr[i] = v;
            }
        }

        // ---- compute: 32 k-steps x 4 n-tiles, LDS.64 fragments ----
        float acc[4][4];
        #pragma unroll
        for (int j = 0; j < 4; j++)
            #pragma unroll
            for (int c = 0; c < 4; c++) acc[j][c] = 0.f;

        const uint2* s2 = reinterpret_cast<const uint2*>(smem);
        #pragma unroll 8
        for (int ks = 0; ks < 32; ks++) {
            int wA = (SX_BASE + (m0 + grp) * KPADW + ks * 8 + 2 * qp) >> 1;
            uint2 aA = s2[wA];                    // a0 (k=qp), a2 (k=qp+4)
            uint2 aB = s2[wA + 4 * KPADW];        // row+8: a1, a3

            #pragma unroll
            for (int j = 0; j < 4; j++) {
                int wB = (SW_BASE + (n0 + j * 8 + grp) * KPADW + ks * 8 + 2 * qp) >> 1;
                uint2 b = s2[wB];                 // b0 (k=qp), b1 (k=qp+4)
                mma_tf32(acc[j], aA.x, aB.x, aA.y, aB.y, b.x, b.y);
            }
        }

        // ---- epilogue ----
        int row_a = node0 + m0 + grp;
        int row_b = row_a + 8;
        #pragma unroll
        for (int j = 0; j < 4; j++) {
            int col = n0 + j * 8 + qp * 2;
            if (row_a < N_NODES) {
                float2 o = make_float2(acc[j][0] + bv[j].x, acc[j][1] + bv[j].y);
                *reinterpret_cast<float2*>(out + (size_t)row_a * D_OUT + col) = o;
            }
            if (row_b < N_NODES) {
                float2 o = make_float2(acc[j][2] + bv[j].x, acc[j][3] + bv[j].y);
                *reinterpret_cast<float2*>(out + (size_t)row_b * D_OUT + col) = o;
            }
        }
        __syncthreads();
        t = tn;
    }
}

// ---------------------------------------------------------------------------
extern "C" void kernel_launch(void* const* d_in, const int* in_sizes, int n_in,
                              void* d_out, int out_size) {
    const float* vdata   = (const float*)d_in[0];
    const float* edata_a = (const float*)d_in[1];
    const float* edata_b = (const float*)d_in[2];
    const int*   conn_a  = (const int*)d_in[3];
    const int*   conn_b  = (const int*)d_in[4];
    const float* W       = (const float*)d_in[5];
    const float* bias    = (const float*)d_in[6];
    float*       out     = (float*)d_out;

    scatter_prep_kernel<<<SCAT_BLOCKS + 128, 256>>>(
        edata_a, conn_a + N_EDGES, edata_b, conn_b + N_EDGES, W);

    {
        size_t smem_bytes = SMEM_WORDS * sizeof(uint32_t);   // 202752
        cudaFuncSetAttribute(gemm_mma_kernel,
                             cudaFuncAttributeMaxDynamicSharedMemorySize,
                             (int)smem_bytes);
        gemm_mma_kernel<<<GRID_P, 512, smem_bytes>>>(vdata, bias, out);
    }
}

// round 11
// speedup vs baseline: 1.2570x; 1.0709x over previous
#include <cuda_runtime.h>
#include <cuda_bf16.h>
#include <cstdint>

#define N_NODES 100000
#define N_EDGES 800000
#define D_IN    256
#define D_OUT   128

#define KPADW   268              // row stride words; 268%32=12 -> scalar LDS conflict-free
#define TILES   1563             // ceil(100000 / 64)
#define GRID_P  148              // persistent CTAs
#define SCAT_BLOCKS 25000        // N_EDGES*16/2/256 (2 edges per thread)

// Aggregation buffer: [N_NODES][128] = [agg_a(0:64) | agg_b(64:128)].
// BSS-zeroed at load; gemm re-zeroes each tile after consuming it.
__device__ __align__(16) float g_x[(size_t)N_NODES * 128];

// W^T tf32 image: [n=128][k=268 padded] (plain layout, no permutation)
__device__ __align__(16) uint32_t g_wt[128 * KPADW];

__device__ __forceinline__ uint32_t f2tf32(float f) {
    uint32_t u;
    asm("cvt.rna.tf32.f32 %0, %1;" : "=r"(u) : "f"(f));
    return u;
}

// ---------------------------------------------------------------------------
// Kernel 1: scatter-add, 2 edges x 2 types per thread (MLP=4) + W prep blocks.
// Edge reads: evict_first; atomics: evict_last (g_x stays L2-resident).
// ---------------------------------------------------------------------------
__global__ void scatter_prep_kernel(const float* __restrict__ edata_a,
                                    const int* __restrict__ recv_a,
                                    const float* __restrict__ edata_b,
                                    const int* __restrict__ recv_b,
                                    const float* __restrict__ W) {
    if (blockIdx.x >= SCAT_BLOCKS) {
        int idx = (blockIdx.x - SCAT_BLOCKS) * 256 + threadIdx.x;
        if (idx < D_IN * D_OUT) {
            int n = idx & 127;
            int k = idx >> 7;
            g_wt[n * KPADW + k] = f2tf32(W[k * D_OUT + n]);
        }
        return;
    }
    int idx  = blockIdx.x * 256 + threadIdx.x;     // 0 .. 6.4M-1
    int q    = idx & 15;
    int e0   = (idx >> 4) * 2;
    int e1   = e0 + 1;

    uint64_t pol_ef, pol_el;
    asm("createpolicy.fractional.L2::evict_first.b64 %0, 1.0;" : "=l"(pol_ef));
    asm("createpolicy.fractional.L2::evict_last.b64 %0, 1.0;"  : "=l"(pol_el));

    const float4* pa0 = reinterpret_cast<const float4*>(edata_a) + (size_t)e0 * 16 + q;
    const float4* pa1 = reinterpret_cast<const float4*>(edata_a) + (size_t)e1 * 16 + q;
    const float4* pb0 = reinterpret_cast<const float4*>(edata_b) + (size_t)e0 * 16 + q;
    const float4* pb1 = reinterpret_cast<const float4*>(edata_b) + (size_t)e1 * 16 + q;
    float4 va0, va1, vb0, vb1;
    asm volatile("ld.global.nc.L2::cache_hint.v4.f32 {%0,%1,%2,%3}, [%4], %5;"
                 : "=f"(va0.x), "=f"(va0.y), "=f"(va0.z), "=f"(va0.w) : "l"(pa0), "l"(pol_ef));
    asm volatile("ld.global.nc.L2::cache_hint.v4.f32 {%0,%1,%2,%3}, [%4], %5;"
                 : "=f"(va1.x), "=f"(va1.y), "=f"(va1.z), "=f"(va1.w) : "l"(pa1), "l"(pol_ef));
    asm volatile("ld.global.nc.L2::cache_hint.v4.f32 {%0,%1,%2,%3}, [%4], %5;"
                 : "=f"(vb0.x), "=f"(vb0.y), "=f"(vb0.z), "=f"(vb0.w) : "l"(pb0), "l"(pol_ef));
    asm volatile("ld.global.nc.L2::cache_hint.v4.f32 {%0,%1,%2,%3}, [%4], %5;"
                 : "=f"(vb1.x), "=f"(vb1.y), "=f"(vb1.z), "=f"(vb1.w) : "l"(pb1), "l"(pol_ef));

    int ra0 = recv_a[e0], ra1 = recv_a[e1];
    int rb0 = recv_b[e0], rb1 = recv_b[e1];
    float* da0 = g_x + (size_t)ra0 * 128 + q * 4;
    float* da1 = g_x + (size_t)ra1 * 128 + q * 4;
    float* db0 = g_x + (size_t)rb0 * 128 + 64 + q * 4;
    float* db1 = g_x + (size_t)rb1 * 128 + 64 + q * 4;

    asm volatile("red.global.L2::cache_hint.add.v4.f32 [%0], {%1,%2,%3,%4}, %5;"
                 :: "l"(da0), "f"(va0.x), "f"(va0.y), "f"(va0.z), "f"(va0.w), "l"(pol_el) : "memory");
    asm volatile("red.global.L2::cache_hint.add.v4.f32 [%0], {%1,%2,%3,%4}, %5;"
                 :: "l"(da1), "f"(va1.x), "f"(va1.y), "f"(va1.z), "f"(va1.w), "l"(pol_el) : "memory");
    asm volatile("red.global.L2::cache_hint.add.v4.f32 [%0], {%1,%2,%3,%4}, %5;"
                 :: "l"(db0), "f"(vb0.x), "f"(vb0.y), "f"(vb0.z), "f"(vb0.w), "l"(pol_el) : "memory");
    asm volatile("red.global.L2::cache_hint.add.v4.f32 [%0], {%1,%2,%3,%4}, %5;"
                 :: "l"(db1), "f"(vb1.x), "f"(vb1.y), "f"(vb1.z), "f"(vb1.w), "l"(pol_el) : "memory");
}

// ---------------------------------------------------------------------------
__device__ __forceinline__ void mma_tf32(float* d, uint32_t a0, uint32_t a1,
                                         uint32_t a2, uint32_t a3,
                                         uint32_t b0, uint32_t b1) {
    asm volatile(
        "mma.sync.aligned.m16n8k8.row.col.f32.tf32.tf32.f32 "
        "{%0,%1,%2,%3}, {%4,%5,%6,%7}, {%8,%9}, {%0,%1,%2,%3};"
        : "+f"(d[0]), "+f"(d[1]), "+f"(d[2]), "+f"(d[3])
        : "r"(a0), "r"(a1), "r"(a2), "r"(a3), "r"(b0), "r"(b1));
}

// SMEM layout (uint32 words): sW [0, 34304), sX [34304, 51456)
#define SW_BASE 0
#define SX_BASE 34304
#define SMEM_WORDS 51456       // 205824 bytes

// ---------------------------------------------------------------------------
// Kernel 2: persistent TF32 HMMA GEMM, warp tile 32x32 (256 B/MMA).
// 256 threads / 8 warps; warp grid 2(M)x4(N) over a 64x128 tile.
// ---------------------------------------------------------------------------
__global__ __launch_bounds__(256, 1)
void gemm_mma_kernel(const float* __restrict__ vdata,
                     const float* __restrict__ bias,
                     float* __restrict__ out) {
    extern __shared__ uint32_t smem[];
    const int tid  = threadIdx.x;
    const int wid  = tid >> 5;
    const int lane = tid & 31;
    const int grp  = lane >> 2;
    const int qp   = lane & 3;

    const int m0 = (wid & 1) * 32;    // warp M band (of 64)
    const int n0 = (wid >> 1) * 32;   // warp N quarter (of 128)

    // ---- Stage W^T image once (34304 words = 8576 uint4) ----
    {
        const uint4* src = reinterpret_cast<const uint4*>(g_wt);
        uint4* dst = reinterpret_cast<uint4*>(smem + SW_BASE);
        #pragma unroll
        for (int i = 0; i < 34; i++) {
            int j = i * 256 + tid;
            if (j < 128 * KPADW / 4) dst[j] = src[j];
        }
    }

    float2 bv[4];
    #pragma unroll
    for (int j = 0; j < 4; j++)
        bv[j] = *reinterpret_cast<const float2*>(bias + n0 + j * 8 + qp * 2);

    const float4* A4 = reinterpret_cast<const float4*>(g_x);
    const float4* V4 = reinterpret_cast<const float4*>(vdata);

    int t = blockIdx.x;
    float4 xr[16];

    if (t < TILES) {
        int node0 = t * 64;
        #pragma unroll
        for (int i = 0; i < 16; i++) {
            int j = i * 256 + tid;
            int r = j >> 6, c4 = j & 63;
            int node = node0 + r;
            float4 v = make_float4(0.f, 0.f, 0.f, 0.f);
            if (node < N_NODES)
                v = (c4 < 32) ? A4[(size_t)node * 32 + c4]
                              : V4[(size_t)node * 32 + (c4 - 32)];
            xr[i] = v;
        }
    }

    while (t < TILES) {
        const int node0 = t * 64;

        // ---- convert regs -> smem tf32 (plain layout, STS.128); re-zero g_x ----
        #pragma unroll
        for (int i = 0; i < 16; i++) {
            int j = i * 256 + tid;
            int r = j >> 6, c4 = j & 63;
            float4 v = xr[i];
            uint4 w = make_uint4(f2tf32(v.x), f2tf32(v.y), f2tf32(v.z), f2tf32(v.w));
            *reinterpret_cast<uint4*>(smem + SX_BASE + r * KPADW + c4 * 4) = w;
            if (c4 < 32) {
                int node = node0 + r;
                if (node < N_NODES)
                    reinterpret_cast<float4*>(g_x)[(size_t)node * 32 + c4] =
                        make_float4(0.f, 0.f, 0.f, 0.f);
            }
        }
        __syncthreads();

        // ---- prefetch next tile during compute ----
        int tn = t + GRID_P;
        if (tn < TILES) {
            int nn0 = tn * 64;
            #pragma unroll
            for (int i = 0; i < 16; i++) {
                int j = i * 256 + tid;
                int r = j >> 6, c4 = j & 63;
                int node = nn0 + r;
                float4 v = make_float4(0.f, 0.f, 0.f, 0.f);
                if (node < N_NODES)
                    v = (c4 < 32) ? A4[(size_t)node * 32 + c4]
                                  : V4[(size_t)node * 32 + (c4 - 32)];
                xr[i] = v;
            }
        }

        // ---- compute: 32 k-steps x (2 m-bands x 4 n-tiles) ----
        float acc[2][4][4];
        #pragma unroll
        for (int mb = 0; mb < 2; mb++)
            #pragma unroll
            for (int j = 0; j < 4; j++)
                #pragma unroll
                for (int c = 0; c < 4; c++) acc[mb][j][c] = 0.f;

        #pragma unroll 4
        for (int ks = 0; ks < 32; ks++) {
            uint32_t a[2][4];
            #pragma unroll
            for (int mb = 0; mb < 2; mb++) {
                int wA = SX_BASE + (m0 + mb * 16 + grp) * KPADW + ks * 8;
                a[mb][0] = smem[wA + qp];
                a[mb][1] = smem[wA + 8 * KPADW + qp];
                a[mb][2] = smem[wA + 4 + qp];
                a[mb][3] = smem[wA + 8 * KPADW + 4 + qp];
            }
            #pragma unroll
            for (int j = 0; j < 4; j++) {
                int wB = SW_BASE + (n0 + j * 8 + grp) * KPADW + ks * 8;
                uint32_t b0 = smem[wB + qp];
                uint32_t b1 = smem[wB + 4 + qp];
                mma_tf32(acc[0][j], a[0][0], a[0][1], a[0][2], a[0][3], b0, b1);
                mma_tf32(acc[1][j], a[1][0], a[1][1], a[1][2], a[1][3], b0, b1);
            }
        }

        // ---- epilogue ----
        #pragma unroll
        for (int mb = 0; mb < 2; mb++) {
            int row_a = node0 + m0 + mb * 16 + grp;
            int row_b = row_a + 8;
            #pragma unroll
            for (int j = 0; j < 4; j++) {
                int col = n0 + j * 8 + qp * 2;
                if (row_a < N_NODES) {
                    float2 o = make_float2(acc[mb][j][0] + bv[j].x,
                                           acc[mb][j][1] + bv[j].y);
                    *reinterpret_cast<float2*>(out + (size_t)row_a * D_OUT + col) = o;
                }
                if (row_b < N_NODES) {
                    float2 o = make_float2(acc[mb][j][2] + bv[j].x,
                                           acc[mb][j][3] + bv[j].y);
                    *reinterpret_cast<float2*>(out + (size_t)row_b * D_OUT + col) = o;
                }
            }
        }
        __syncthreads();
        t = tn;
    }
}

// ---------------------------------------------------------------------------
extern "C" void kernel_launch(void* const* d_in, const int* in_sizes, int n_in,
                              void* d_out, int out_size) {
    const float* vdata   = (const float*)d_in[0];
    const float* edata_a = (const float*)d_in[1];
    const float* edata_b = (const float*)d_in[2];
    const int*   conn_a  = (const int*)d_in[3];
    const int*   conn_b  = (const int*)d_in[4];
    const float* W       = (const float*)d_in[5];
    const float* bias    = (const float*)d_in[6];
    float*       out     = (float*)d_out;

    scatter_prep_kernel<<<SCAT_BLOCKS + 128, 256>>>(
        edata_a, conn_a + N_EDGES, edata_b, conn_b + N_EDGES, W);

    {
        size_t smem_bytes = SMEM_WORDS * sizeof(uint32_t);   // 205824
        cudaFuncSetAttribute(gemm_mma_kernel,
                             cudaFuncAttributeMaxDynamicSharedMemorySize,
                             (int)smem_bytes);
        gemm_mma_kernel<<<GRID_P, 256, smem_bytes>>>(vdata, bias, out);
    }
}